// round 3
// baseline (speedup 1.0000x reference)
#include <cuda_runtime.h>
#include <cstdint>

// sMPS transfer-matrix contraction.
// N=2048 batch, L=64 sites, CHI=64 bond, D=2, MIU2=4.
// E'(n) = sum_m T_m^T E(n) T_m,  T_m = x0*A[m,:,0,:] + x1*A[m,:,1,:]
// E symmetric for all steps -> read E[r][d] as E[d][r] (row-contiguous).
// One CTA = 2 batch elements packed as float2 lanes; all math is fma.rn.f32x2.

typedef unsigned long long u64;

#define PITCH 66                 // float2 pitch for 64-wide rows (16B-aligned rows, depadded banks)
#define NTOT  2048
#define LSITE 64

__device__ __forceinline__ u64 fma2(u64 a, u64 b, u64 c) {
    u64 d;
    asm("fma.rn.f32x2 %0, %1, %2, %3;" : "=l"(d) : "l"(a), "l"(b), "l"(c));
    return d;
}

__global__ void __launch_bounds__(256, 2)
smps_kernel(const float* __restrict__ x,
            const float* __restrict__ mps0,
            const float* __restrict__ mpsm,
            const float* __restrict__ mpsl,
            float* __restrict__ out)
{
    extern __shared__ float2 sm[];
    float2* Es = sm;                   // 64 x PITCH : E state (float2 = two batch lanes)
    float2* Ts = Es + 64 * PITCH;      // 64 x PITCH : T_m scratch / t0 / v
    float2* Fs = Ts + 64 * PITCH;      // 64 x PITCH : F = E*T scratch
    float2* xs = Fs + 64 * PITCH;      // 128        : x rows for both lanes

    const int tid = threadIdx.x;
    const int n0  = blockIdx.x * 2;
    const int r0  = (tid >> 4) * 4;    // C-tile rows
    const int c0  = (tid & 15) * 4;    // C-tile cols

    // ---- preload x[n0,:,:] and x[n0+1,:,:] (128 floats each) ----
    if (tid < 128) {
        xs[tid] = make_float2(x[(size_t)n0 * 128 + tid],
                              x[(size_t)(n0 + 1) * 128 + tid]);
    }
    __syncthreads();

    // ---- initial site: t0[a][d] = mps0[a,0,0,d]*x0 + mps0[a,0,1,d]*x1 ----
    {
        int a = tid >> 6, d = tid & 63;
        float w0 = mps0[(a * 2 + 0) * 64 + d];
        float w1 = mps0[(a * 2 + 1) * 64 + d];
        float2 xc0 = xs[0], xc1 = xs[1];
        Ts[a * PITCH + d] = make_float2(w0 * xc0.x + w1 * xc1.x,
                                        w0 * xc0.y + w1 * xc1.y);
    }
    __syncthreads();

    // ---- E0[r][c] = sum_a t0[a][r] * t0[a][c] ----
    #pragma unroll
    for (int i = 0; i < 4; i++) {
        #pragma unroll
        for (int j = 0; j < 4; j++) {
            float2 acc = make_float2(0.f, 0.f);
            #pragma unroll
            for (int a = 0; a < 4; a++) {
                float2 u = Ts[a * PITCH + r0 + i];
                float2 v = Ts[a * PITCH + c0 + j];
                acc.x += u.x * v.x;
                acc.y += u.y * v.y;
            }
            Es[(r0 + i) * PITCH + c0 + j] = acc;
        }
    }
    __syncthreads();

    // ---- 62 mid layers ----
    for (int l = 1; l <= 62; ++l) {
        const float* Al = mpsm + (size_t)(l - 1) * 4 * 64 * 128;  // [m][b][c][d]
        const float2 xc0 = xs[2 * l];
        const float2 xc1 = xs[2 * l + 1];

        u64 eacc[4][4] = {};   // E' accumulator (packed 0.0f pairs)

        #pragma unroll 1
        for (int m = 0; m < 4; ++m) {
            // --- build T_m[b][d] = A[m,b,0,d]*x0 + A[m,b,1,d]*x1 (both lanes) ---
            #pragma unroll
            for (int e = 0; e < 4; ++e) {
                int base = tid + 256 * e;          // 0..1023 -> (b, d-quad)
                int b = base >> 4;
                int q = base & 15;
                const float4* Ap = reinterpret_cast<const float4*>(Al + ((size_t)m * 64 + b) * 128);
                float4 a0 = Ap[q];                 // c = 0
                float4 a1 = Ap[q + 16];            // c = 1
                float2* tr = &Ts[b * PITCH + q * 4];
                tr[0] = make_float2(a0.x * xc0.x + a1.x * xc1.x, a0.x * xc0.y + a1.x * xc1.y);
                tr[1] = make_float2(a0.y * xc0.x + a1.y * xc1.x, a0.y * xc0.y + a1.y * xc1.y);
                tr[2] = make_float2(a0.z * xc0.x + a1.z * xc1.x, a0.z * xc0.y + a1.z * xc1.y);
                tr[3] = make_float2(a0.w * xc0.x + a1.w * xc1.x, a0.w * xc0.y + a1.w * xc1.y);
            }
            __syncthreads();

            // --- GEMM1: F[r][c] = sum_d E[r][d]*T[d][c]; read E[r][d] as Es[d][r] (symmetry) ---
            u64 acc[4][4] = {};
            #pragma unroll 4
            for (int d = 0; d < 64; ++d) {
                ulonglong2 aA = *reinterpret_cast<const ulonglong2*>(&Es[d * PITCH + r0]);
                ulonglong2 aB = *reinterpret_cast<const ulonglong2*>(&Es[d * PITCH + r0 + 2]);
                ulonglong2 bA = *reinterpret_cast<const ulonglong2*>(&Ts[d * PITCH + c0]);
                ulonglong2 bB = *reinterpret_cast<const ulonglong2*>(&Ts[d * PITCH + c0 + 2]);
                u64 av[4] = {aA.x, aA.y, aB.x, aB.y};
                u64 bv[4] = {bA.x, bA.y, bB.x, bB.y};
                #pragma unroll
                for (int i = 0; i < 4; i++)
                    #pragma unroll
                    for (int j = 0; j < 4; j++)
                        acc[i][j] = fma2(av[i], bv[j], acc[i][j]);
            }
            // store F tile (prev readers of Fs were before last barrier)
            #pragma unroll
            for (int i = 0; i < 4; i++) {
                *reinterpret_cast<ulonglong2*>(&Fs[(r0 + i) * PITCH + c0]) =
                    make_ulonglong2(acc[i][0], acc[i][1]);
                *reinterpret_cast<ulonglong2*>(&Fs[(r0 + i) * PITCH + c0 + 2]) =
                    make_ulonglong2(acc[i][2], acc[i][3]);
            }
            __syncthreads();

            // --- GEMM2: E'[f][g] += sum_b T[b][f]*F[b][g] ---
            #pragma unroll 4
            for (int b = 0; b < 64; ++b) {
                ulonglong2 aA = *reinterpret_cast<const ulonglong2*>(&Ts[b * PITCH + r0]);
                ulonglong2 aB = *reinterpret_cast<const ulonglong2*>(&Ts[b * PITCH + r0 + 2]);
                ulonglong2 bA = *reinterpret_cast<const ulonglong2*>(&Fs[b * PITCH + c0]);
                ulonglong2 bB = *reinterpret_cast<const ulonglong2*>(&Fs[b * PITCH + c0 + 2]);
                u64 av[4] = {aA.x, aA.y, aB.x, aB.y};
                u64 bv[4] = {bA.x, bA.y, bB.x, bB.y};
                #pragma unroll
                for (int i = 0; i < 4; i++)
                    #pragma unroll
                    for (int j = 0; j < 4; j++)
                        eacc[i][j] = fma2(av[i], bv[j], eacc[i][j]);
            }
            __syncthreads();   // protects Ts (next build) and Fs (next GEMM1 store)
        }

        // --- write E' back into Es ---
        #pragma unroll
        for (int i = 0; i < 4; i++) {
            *reinterpret_cast<ulonglong2*>(&Es[(r0 + i) * PITCH + c0]) =
                make_ulonglong2(eacc[i][0], eacc[i][1]);
            *reinterpret_cast<ulonglong2*>(&Es[(r0 + i) * PITCH + c0 + 2]) =
                make_ulonglong2(eacc[i][2], eacc[i][3]);
        }
        __syncthreads();
    }

    // ---- last site: v[m][b] = mpsl[m,b,0,0]*x0 + mpsl[m,b,1,0]*x1 ----
    {
        int m = tid >> 6, b = tid & 63;
        float w0 = mpsl[(m * 64 + b) * 2 + 0];
        float w1 = mpsl[(m * 64 + b) * 2 + 1];
        float2 xc0 = xs[2 * 63], xc1 = xs[2 * 63 + 1];
        Ts[m * PITCH + b] = make_float2(w0 * xc0.x + w1 * xc1.x,
                                        w0 * xc0.y + w1 * xc1.y);
    }
    __syncthreads();

    // ---- p = |sum_m v_m^T E v_m|, two lanes ----
    float2 part;
    {
        int m = tid >> 6, d = tid & 63;
        float2 u = make_float2(0.f, 0.f);
        #pragma unroll 4
        for (int b = 0; b < 64; ++b) {
            float2 v = Ts[m * PITCH + b];
            float2 e = Es[b * PITCH + d];
            u.x += v.x * e.x;
            u.y += v.y * e.y;
        }
        float2 vd = Ts[m * PITCH + d];
        part = make_float2(u.x * vd.x, u.y * vd.y);
    }
    // block reduction over 256 threads
    #pragma unroll
    for (int off = 16; off > 0; off >>= 1) {
        part.x += __shfl_down_sync(0xffffffffu, part.x, off);
        part.y += __shfl_down_sync(0xffffffffu, part.y, off);
    }
    __syncthreads();           // Fs reuse as reduction scratch
    if ((tid & 31) == 0) Fs[tid >> 5] = part;
    __syncthreads();
    if (tid == 0) {
        float2 s = make_float2(0.f, 0.f);
        #pragma unroll
        for (int w = 0; w < 8; ++w) { s.x += Fs[w].x; s.y += Fs[w].y; }
        out[n0]     = fabsf(s.x);
        out[n0 + 1] = fabsf(s.y);
    }
}

extern "C" void kernel_launch(void* const* d_in, const int* in_sizes, int n_in,
                              void* d_out, int out_size)
{
    const float* x    = (const float*)d_in[0];   // (2048, 64, 2)
    const float* mps0 = (const float*)d_in[1];   // (4, 1, 2, 64)
    const float* mpsm = (const float*)d_in[2];   // (62, 4, 64, 2, 64)
    const float* mpsl = (const float*)d_in[3];   // (4, 64, 2, 1)
    float* out = (float*)d_out;                  // (2048, 1)

    size_t smem = (size_t)3 * 64 * PITCH * sizeof(float2) + 128 * sizeof(float2);
    cudaFuncSetAttribute(smps_kernel, cudaFuncAttributeMaxDynamicSharedMemorySize, (int)smem);
    smps_kernel<<<NTOT / 2, 256, smem>>>(x, mps0, mpsm, mpsl, out);
}

// round 4
// speedup vs baseline: 1.5523x; 1.5523x over previous
#include <cuda_runtime.h>
#include <cstdint>

// sMPS transfer-matrix contraction.
// N=2048 batch, L=64 sites, CHI=64 bond, D=2, MIU2=4.
// E'(n) = sum_m T_m^T E(n) T_m,  T_m = x0*A[m,:,0,:] + x1*A[m,:,1,:]
// E symmetric for all steps -> read E[r][d] as E[d][r] (row-contiguous).
// One CTA = 2 batch elements packed as float2 lanes; all math is fma.rn.f32x2.
// R4: tile remap {2i,2i+1,32+2i,32+2i+1} -> all LDS/STS lane-contiguous,
//     eliminating the 4-way bank conflicts measured in R3 (l1tex 97.8%).

typedef unsigned long long u64;

#define PITCH 66                 // float2 pitch for 64-wide rows
#define NTOT  2048

__device__ __forceinline__ u64 fma2(u64 a, u64 b, u64 c) {
    u64 d;
    asm("fma.rn.f32x2 %0, %1, %2, %3;" : "=l"(d) : "l"(a), "l"(b), "l"(c));
    return d;
}

__global__ void __launch_bounds__(256, 2)
smps_kernel(const float* __restrict__ x,
            const float* __restrict__ mps0,
            const float* __restrict__ mpsm,
            const float* __restrict__ mpsl,
            float* __restrict__ out)
{
    extern __shared__ float2 sm[];
    float2* Es = sm;                   // 64 x PITCH : E state (float2 = two batch lanes)
    float2* Ts = Es + 64 * PITCH;      // 64 x PITCH : T_m scratch / t0 / v
    float2* Fs = Ts + 64 * PITCH;      // 64 x PITCH : F = E*T scratch
    float2* xs = Fs + 64 * PITCH;      // 128        : x rows for both lanes

    const int tid = threadIdx.x;
    const int n0  = blockIdx.x * 2;
    const int ri  = tid >> 4;          // 0..15
    const int ci  = tid & 15;          // 0..15
    const int rA  = 2 * ri,  rB = 32 + 2 * ri;   // row pairs owned by this thread
    const int cA  = 2 * ci,  cB = 32 + 2 * ci;   // col pairs owned by this thread
    const int R[4] = { rA, rA + 1, rB, rB + 1 };
    const int C[4] = { cA, cA + 1, cB, cB + 1 };

    // ---- preload x[n0,:,:] and x[n0+1,:,:] (128 floats each) ----
    if (tid < 128) {
        xs[tid] = make_float2(x[(size_t)n0 * 128 + tid],
                              x[(size_t)(n0 + 1) * 128 + tid]);
    }
    __syncthreads();

    // ---- initial site: t0[a][d] = mps0[a,0,0,d]*x0 + mps0[a,0,1,d]*x1 ----
    {
        int a = tid >> 6, d = tid & 63;
        float w0 = mps0[(a * 2 + 0) * 64 + d];
        float w1 = mps0[(a * 2 + 1) * 64 + d];
        float2 xc0 = xs[0], xc1 = xs[1];
        Ts[a * PITCH + d] = make_float2(w0 * xc0.x + w1 * xc1.x,
                                        w0 * xc0.y + w1 * xc1.y);
    }
    __syncthreads();

    // ---- E0[r][c] = sum_a t0[a][r] * t0[a][c] ----
    #pragma unroll
    for (int i = 0; i < 4; i++) {
        #pragma unroll
        for (int j = 0; j < 4; j++) {
            float2 acc = make_float2(0.f, 0.f);
            #pragma unroll
            for (int a = 0; a < 4; a++) {
                float2 u = Ts[a * PITCH + R[i]];
                float2 v = Ts[a * PITCH + C[j]];
                acc.x += u.x * v.x;
                acc.y += u.y * v.y;
            }
            Es[R[i] * PITCH + C[j]] = acc;
        }
    }
    __syncthreads();

    // ---- 62 mid layers ----
    for (int l = 1; l <= 62; ++l) {
        const float* Al = mpsm + (size_t)(l - 1) * 4 * 64 * 128;  // [m][b][c][d]
        const float2 xc0 = xs[2 * l];
        const float2 xc1 = xs[2 * l + 1];

        u64 eacc[4][4] = {};   // E' accumulator (packed 0.0f pairs)

        #pragma unroll 1
        for (int m = 0; m < 4; ++m) {
            // --- build T_m[b][d] = A[m,b,0,d]*x0 + A[m,b,1,d]*x1 (both lanes) ---
            // thread (ri,ci) fills row b = ri+16e, col pairs {cA,cA+1} and {cB,cB+1}:
            // 16-lane store groups are contiguous 256B -> conflict-free STS.128.
            #pragma unroll
            for (int e = 0; e < 4; ++e) {
                int b = ri + 16 * e;
                const float* Ar = Al + ((size_t)m * 64 + b) * 128;
                float2 p0 = *reinterpret_cast<const float2*>(Ar + cA);        // c=0
                float2 p1 = *reinterpret_cast<const float2*>(Ar + 64 + cA);   // c=1
                float2 q0 = *reinterpret_cast<const float2*>(Ar + cB);
                float2 q1 = *reinterpret_cast<const float2*>(Ar + 64 + cB);
                float4 ta, tb;
                ta.x = p0.x * xc0.x + p1.x * xc1.x;  ta.y = p0.x * xc0.y + p1.x * xc1.y;
                ta.z = p0.y * xc0.x + p1.y * xc1.x;  ta.w = p0.y * xc0.y + p1.y * xc1.y;
                tb.x = q0.x * xc0.x + q1.x * xc1.x;  tb.y = q0.x * xc0.y + q1.x * xc1.y;
                tb.z = q0.y * xc0.x + q1.y * xc1.x;  tb.w = q0.y * xc0.y + q1.y * xc1.y;
                *reinterpret_cast<float4*>(&Ts[b * PITCH + cA]) = ta;
                *reinterpret_cast<float4*>(&Ts[b * PITCH + cB]) = tb;
            }
            __syncthreads();

            // --- GEMM1: F[r][c] = sum_d E[r][d]*T[d][c]; read E[r][d] as Es[d][r] (symmetry) ---
            u64 acc[4][4] = {};
            #pragma unroll 4
            for (int d = 0; d < 64; ++d) {
                ulonglong2 aA = *reinterpret_cast<const ulonglong2*>(&Es[d * PITCH + rA]);
                ulonglong2 aB = *reinterpret_cast<const ulonglong2*>(&Es[d * PITCH + rB]);
                ulonglong2 bA = *reinterpret_cast<const ulonglong2*>(&Ts[d * PITCH + cA]);
                ulonglong2 bB = *reinterpret_cast<const ulonglong2*>(&Ts[d * PITCH + cB]);
                u64 av[4] = {aA.x, aA.y, aB.x, aB.y};
                u64 bv[4] = {bA.x, bA.y, bB.x, bB.y};
                #pragma unroll
                for (int i = 0; i < 4; i++)
                    #pragma unroll
                    for (int j = 0; j < 4; j++)
                        acc[i][j] = fma2(av[i], bv[j], acc[i][j]);
            }
            // store F tile: per row, two contiguous 16B stores (cols cA..cA+1, cB..cB+1)
            #pragma unroll
            for (int i = 0; i < 4; i++) {
                *reinterpret_cast<ulonglong2*>(&Fs[R[i] * PITCH + cA]) =
                    make_ulonglong2(acc[i][0], acc[i][1]);
                *reinterpret_cast<ulonglong2*>(&Fs[R[i] * PITCH + cB]) =
                    make_ulonglong2(acc[i][2], acc[i][3]);
            }
            __syncthreads();

            // --- GEMM2: E'[f][g] += sum_b T[b][f]*F[b][g] ---
            #pragma unroll 4
            for (int b = 0; b < 64; ++b) {
                ulonglong2 aA = *reinterpret_cast<const ulonglong2*>(&Ts[b * PITCH + rA]);
                ulonglong2 aB = *reinterpret_cast<const ulonglong2*>(&Ts[b * PITCH + rB]);
                ulonglong2 bA = *reinterpret_cast<const ulonglong2*>(&Fs[b * PITCH + cA]);
                ulonglong2 bB = *reinterpret_cast<const ulonglong2*>(&Fs[b * PITCH + cB]);
                u64 av[4] = {aA.x, aA.y, aB.x, aB.y};
                u64 bv[4] = {bA.x, bA.y, bB.x, bB.y};
                #pragma unroll
                for (int i = 0; i < 4; i++)
                    #pragma unroll
                    for (int j = 0; j < 4; j++)
                        eacc[i][j] = fma2(av[i], bv[j], eacc[i][j]);
            }
            __syncthreads();   // protects Ts (next build) and Fs (next GEMM1 store)
        }

        // --- write E' back into Es ---
        #pragma unroll
        for (int i = 0; i < 4; i++) {
            *reinterpret_cast<ulonglong2*>(&Es[R[i] * PITCH + cA]) =
                make_ulonglong2(eacc[i][0], eacc[i][1]);
            *reinterpret_cast<ulonglong2*>(&Es[R[i] * PITCH + cB]) =
                make_ulonglong2(eacc[i][2], eacc[i][3]);
        }
        __syncthreads();
    }

    // ---- last site: v[m][b] = mpsl[m,b,0,0]*x0 + mpsl[m,b,1,0]*x1 ----
    {
        int m = tid >> 6, b = tid & 63;
        float w0 = mpsl[(m * 64 + b) * 2 + 0];
        float w1 = mpsl[(m * 64 + b) * 2 + 1];
        float2 xc0 = xs[2 * 63], xc1 = xs[2 * 63 + 1];
        Ts[m * PITCH + b] = make_float2(w0 * xc0.x + w1 * xc1.x,
                                        w0 * xc0.y + w1 * xc1.y);
    }
    __syncthreads();

    // ---- p = |sum_m v_m^T E v_m|, two lanes ----
    float2 part;
    {
        int m = tid >> 6, d = tid & 63;
        float2 u = make_float2(0.f, 0.f);
        #pragma unroll 4
        for (int b = 0; b < 64; ++b) {
            float2 v = Ts[m * PITCH + b];
            float2 e = Es[b * PITCH + d];
            u.x += v.x * e.x;
            u.y += v.y * e.y;
        }
        float2 vd = Ts[m * PITCH + d];
        part = make_float2(u.x * vd.x, u.y * vd.y);
    }
    // block reduction over 256 threads
    #pragma unroll
    for (int off = 16; off > 0; off >>= 1) {
        part.x += __shfl_down_sync(0xffffffffu, part.x, off);
        part.y += __shfl_down_sync(0xffffffffu, part.y, off);
    }
    __syncthreads();           // Fs reuse as reduction scratch
    if ((tid & 31) == 0) Fs[tid >> 5] = part;
    __syncthreads();
    if (tid == 0) {
        float2 s = make_float2(0.f, 0.f);
        #pragma unroll
        for (int w = 0; w < 8; ++w) { s.x += Fs[w].x; s.y += Fs[w].y; }
        out[n0]     = fabsf(s.x);
        out[n0 + 1] = fabsf(s.y);
    }
}

extern "C" void kernel_launch(void* const* d_in, const int* in_sizes, int n_in,
                              void* d_out, int out_size)
{
    const float* x    = (const float*)d_in[0];   // (2048, 64, 2)
    const float* mps0 = (const float*)d_in[1];   // (4, 1, 2, 64)
    const float* mpsm = (const float*)d_in[2];   // (62, 4, 64, 2, 64)
    const float* mpsl = (const float*)d_in[3];   // (4, 64, 2, 1)
    float* out = (float*)d_out;                  // (2048, 1)

    size_t smem = (size_t)3 * 64 * PITCH * sizeof(float2) + 128 * sizeof(float2);
    cudaFuncSetAttribute(smps_kernel, cudaFuncAttributeMaxDynamicSharedMemorySize, (int)smem);
    smps_kernel<<<NTOT / 2, 256, smem>>>(x, mps0, mpsm, mpsl, out);
}